// round 13
// baseline (speedup 1.0000x reference)
#include <cuda_runtime.h>
#include <cstdint>

#define NUM_ANCHORS 145152
#define NUM_CH 85
#define INV_IMG (1.0f / 1536.0f)
#define ROWS_PER_TILE 64
#define THREADS 128
#define DEPTH 3
#define NUM_TILES (NUM_ANCHORS / ROWS_PER_TILE)        // 2268
#define TILE_FLOATS (ROWS_PER_TILE * NUM_CH)           // 5440
#define TILE_BYTES (TILE_FLOATS * 4)                   // 21760
#define SMEM_BYTES (128 + DEPTH * TILE_BYTES)          // 65408 B

// d_out layout (fp32), reference tuple order, flattened:
//   [0 .. 4N)    bboxes     (N,4) = x0, y0, x1, y1
//   [4N .. 5N)   scores     (N,)
//   [5N .. 6N)   class_pred (N,)  (as float)
//   [6N .. 12N)  detections (N,6) = x0, y0, x1, y1, conf, cls

__device__ __forceinline__ unsigned smem_u32(const void* p) {
    unsigned a;
    asm("{ .reg .u64 t; cvta.to.shared.u64 t, %1; cvt.u32.u64 %0, t; }"
        : "=r"(a) : "l"(p));
    return a;
}

__device__ __forceinline__ void mbar_init(unsigned mbar, unsigned count) {
    asm volatile("mbarrier.init.shared.b64 [%0], %1;" :: "r"(mbar), "r"(count)
                 : "memory");
}

__device__ __forceinline__ void mbar_expect_tx(unsigned mbar, unsigned bytes) {
    asm volatile("mbarrier.arrive.expect_tx.shared.b64 _, [%0], %1;"
                 :: "r"(mbar), "r"(bytes) : "memory");
}

// One-shot bulk copy gmem -> smem (async proxy), completion on mbar.
__device__ __forceinline__ void bulk_load(unsigned dst, const void* src,
                                          unsigned bytes, unsigned mbar) {
    asm volatile(
        "cp.async.bulk.shared::cta.global.mbarrier::complete_tx::bytes "
        "[%0], [%1], %2, [%3];"
        :: "r"(dst), "l"(src), "r"(bytes), "r"(mbar) : "memory");
}

__device__ __forceinline__ void mbar_wait(unsigned mbar, unsigned phase) {
    unsigned done;
    asm volatile(
        "{\n\t"
        ".reg .pred p;\n\t"
        "mbarrier.try_wait.parity.acquire.cta.shared::cta.b64 p, [%1], %2;\n\t"
        "selp.b32 %0, 1, 0, p;\n\t"
        "}"
        : "=r"(done) : "r"(mbar), "r"(phase) : "memory");
    if (!done) {
        asm volatile(
            "{\n\t"
            ".reg .pred P1;\n\t"
            "WL_%=:\n\t"
            "mbarrier.try_wait.parity.acquire.cta.shared::cta.b64 P1, [%0], %1, 0x989680;\n\t"
            "@P1 bra.uni WD_%=;\n\t"
            "bra.uni WL_%=;\n\t"
            "WD_%=:\n\t"
            "}"
            :: "r"(mbar), "r"(phase) : "memory");
    }
}

// Pair-lane decode: 2 threads per row; even lane ch 0..39, odd lane 40..79.
__device__ __forceinline__ void compute_tile(const float* __restrict__ s_base,
                                             float* __restrict__ out,
                                             int tile, int tid)
{
    const unsigned FULL = 0xffffffffu;
    const int row  = tid >> 1;                // 0..63
    const int half = tid & 1;
    const float* s = s_base + row * NUM_CH;   // stride 85 -> conflict-free
    const int anchor = tile * ROWS_PER_TILE + row;

    float cx  = s[0];
    float cy  = s[1];
    float w   = s[2];
    float h   = s[3];
    float obj = s[4];

    // 40-channel scan per lane, strict > keeps lowest index on ties.
    const int base = 40 * half;
    const float* cs = s + 5 + base;
    float bv = cs[0];
    int   bi = base;
    #pragma unroll
    for (int k = 1; k < 40; ++k) {
        float v = cs[k];
        if (v > bv) { bv = v; bi = base + k; }
    }

    // Combine pair halves (lowest index wins ties).
    float ov = __shfl_xor_sync(FULL, bv, 1);
    int   oi = __shfl_xor_sync(FULL, bi, 1);
    if (ov > bv || (ov == bv && oi < bi)) { bv = ov; bi = oi; }

    float bx = cx * INV_IMG;
    float by = cy * INV_IMG;
    float bw = w  * INV_IMG;
    float bh = h  * INV_IMG;
    float x0 = bx - bw * 0.5f;
    float y0 = by - bh * 0.5f;
    float x1 = bx + bw * 0.5f;
    float y1 = by + bh * 0.5f;

    float conf  = bv;
    float clsf  = (float)bi;
    float score = obj * conf;

    float* out_sc  = out + (long long)NUM_ANCHORS * 4;
    float* out_cls = out + (long long)NUM_ANCHORS * 5;
    float* out_det = out + (long long)NUM_ANCHORS * 6;

    if (half == 0) {
        ((float4*)out)[anchor] = make_float4(x0, y0, x1, y1);
        out_sc[anchor]  = score;
        out_cls[anchor] = clsf;
    } else {
        float2* det = (float2*)(out_det + (long long)anchor * 6);
        det[0] = make_float2(x0, y0);
        det[1] = make_float2(x1, y1);
        det[2] = make_float2(conf, clsf);
    }
}

__global__ __launch_bounds__(THREADS)
void yolo_decode_kernel(const float* __restrict__ pred,
                        float* __restrict__ out,
                        int n_blocks_total)
{
    extern __shared__ float smem[];
    char* sbase = (char*)smem;
    unsigned mbar[DEPTH];
    float*   bufs[DEPTH];
    unsigned dsts[DEPTH];
    #pragma unroll
    for (int k = 0; k < DEPTH; ++k) {
        mbar[k] = smem_u32(sbase + 8 * k);
        bufs[k] = (float*)(sbase + 128) + k * TILE_FLOATS;
        dsts[k] = smem_u32(bufs[k]);
    }

    const int tid = threadIdx.x;

    if (tid == 0) {
        #pragma unroll
        for (int k = 0; k < DEPTH; ++k) mbar_init(mbar[k], 1);
        asm volatile("fence.proxy.async.shared::cta;" ::: "memory");
    }
    __syncthreads();

    if (blockIdx.x >= NUM_TILES) return;

    int phase[DEPTH];
    #pragma unroll
    for (int k = 0; k < DEPTH; ++k) phase[k] = 0;

    // ---- Prologue: DEPTH-1 tile loads in flight ----
    if (tid == 0) {
        #pragma unroll
        for (int k = 0; k < DEPTH - 1; ++k) {
            int t = blockIdx.x + k * n_blocks_total;
            if (t < NUM_TILES) {
                mbar_expect_tx(mbar[k], TILE_BYTES);
                bulk_load(dsts[k], pred + (long long)t * TILE_FLOATS,
                          TILE_BYTES, mbar[k]);
            }
        }
    }

    // ---- Steady state: up to DEPTH-1 bulk copies pending during compute ----
    int slot = 0;
    for (int t = blockIdx.x; t < NUM_TILES; t += n_blocks_total) {
        // issue prefetch for t + (DEPTH-1)*stride into slot (slot+DEPTH-1)%DEPTH
        int pf = t + (DEPTH - 1) * n_blocks_total;
        int ps = slot + (DEPTH - 1);
        if (ps >= DEPTH) ps -= DEPTH;
        if (pf < NUM_TILES && tid == 0) {
            mbar_expect_tx(mbar[ps], TILE_BYTES);
            bulk_load(dsts[ps], pred + (long long)pf * TILE_FLOATS,
                      TILE_BYTES, mbar[ps]);
        }

        mbar_wait(mbar[slot], phase[slot]);
        phase[slot] ^= 1;

        compute_tile(bufs[slot], out, t, tid);

        // all threads must finish reading this slot before it is re-targeted
        // by the prefetch issued DEPTH-1 iterations from now
        __syncthreads();

        if (++slot == DEPTH) slot = 0;
    }
}

extern "C" void kernel_launch(void* const* d_in, const int* in_sizes, int n_in,
                              void* d_out, int out_size)
{
    const float* pred = (const float*)d_in[0];
    // d_in[1] = score_threshold — unused by the reference computation.
    float* out = (float*)d_out;

    cudaFuncSetAttribute(yolo_decode_kernel,
                         cudaFuncAttributeMaxDynamicSharedMemorySize,
                         SMEM_BYTES);

    const int blocks = 444;                 // 3 per SM, persistent grid-stride
    yolo_decode_kernel<<<blocks, THREADS, SMEM_BYTES>>>(pred, out, blocks);
}